// round 11
// baseline (speedup 1.0000x reference)
#include <cuda_runtime.h>
#include <cuda_fp16.h>
#include <cstdint>

// ============================================================
// QuaternionLinear via 12-mult Cayley-Dickson/Gauss decomposition,
// single-accumulator version: the shared Gauss term (K-blocks 0-1)
// is snapshotted to global fp32 (g_S) and reloaded, freeing enough
// registers for the efficient 64x64 warp tile / BN=256 geometry.
//   variant0 (out_r,out_i): B0=[br|-bj|-(br+bi)|bj-bk|bi-br|bj+bk]
//   variant1 (out_j,out_k): B1=[bj|br|-(bj+bk)|bi-br|bk-bj|-(br+bi)]
//   A planes: q = [ar+ai, aj+ak, ai, ak, ar, aj]
//   acc: blocks 0..1 -> snapshot S; +blocks 2..3 -> comp zc;
//        acc<-S; +blocks 4..5 -> comp zc+1.
// ============================================================

#define BATCH   4096
#define KTOT    6144
#define NOUT    1024

#define BM      128
#define BN      256
#define BK      64            // halves per K-tile (128B rows)
#define NK      (KTOT / BK)   // 96
#define STAGES  3
#define NTHREADS 256

#define A_TILE_BYTES (BM * 128)   // 16384
#define B_TILE_BYTES (BN * 128)   // 32768
#define STAGE_BYTES  (A_TILE_BYTES + B_TILE_BYTES)   // 49152
#define SMEM_TOTAL   (STAGES * STAGE_BYTES)          // 147456

// device-global scratch (allocation-free per harness rules)
__device__ __align__(128) __half g_A [(size_t)BATCH * KTOT];     // 50.3 MB
__device__ __align__(128) __half g_B0[(size_t)NOUT  * KTOT];     // 12.6 MB
__device__ __align__(128) __half g_B1[(size_t)NOUT  * KTOT];     // 12.6 MB
__device__ __align__(128) float  g_S [(size_t)256 * BM * BN];    // 33.5 MB

// ---------------- helpers ----------------
__device__ __forceinline__ uint32_t smem_u32(const void* p) {
    uint32_t a;
    asm("{ .reg .u64 t; cvta.to.shared.u64 t, %1; cvt.u32.u64 %0, t; }" : "=r"(a) : "l"(p));
    return a;
}
__device__ __forceinline__ void cp_async16(uint32_t dst, const void* src) {
    asm volatile("cp.async.cg.shared.global [%0], [%1], 16;\n" :: "r"(dst), "l"(src));
}
#define CP_COMMIT() asm volatile("cp.async.commit_group;\n" ::: "memory")
#define CP_WAIT(n)  asm volatile("cp.async.wait_group %0;\n" :: "n"(n) : "memory")

__device__ __forceinline__ void ldm_x4(uint32_t* r, uint32_t addr) {
    asm volatile("ldmatrix.sync.aligned.m8n8.x4.shared.b16 {%0,%1,%2,%3}, [%4];"
        : "=r"(r[0]), "=r"(r[1]), "=r"(r[2]), "=r"(r[3]) : "r"(addr));
}
__device__ __forceinline__ void mma16816(float* c, const uint32_t* a, const uint32_t* b) {
    asm volatile(
        "mma.sync.aligned.m16n8k16.row.col.f32.f16.f16.f32 "
        "{%0,%1,%2,%3}, {%4,%5,%6,%7}, {%8,%9}, {%0,%1,%2,%3};"
        : "+f"(c[0]), "+f"(c[1]), "+f"(c[2]), "+f"(c[3])
        : "r"(a[0]), "r"(a[1]), "r"(a[2]), "r"(a[3]), "r"(b[0]), "r"(b[1]));
}
__device__ __forceinline__ uint32_t sw128(uint32_t off) {
    return off ^ ((off >> 3) & 0x70);
}
__device__ __forceinline__ __half2 h2(float a, float b) { return __floats2half2_rn(a, b); }

// ---------------- Prep: A planes ----------------
__global__ void prep_a_kernel(const float4* __restrict__ x) {
    int t = blockIdx.x * blockDim.x + threadIdx.x;
    if (t >= BATCH * 512) return;
    int b  = t >> 9;
    int ip = (t & 511) << 1;
    const float4* xr = x + ((size_t)b * 1024 + ip);
    float4 v0 = xr[0], v1 = xr[1];
    __half* row = g_A + (size_t)b * KTOT;
    *reinterpret_cast<__half2*>(row +    0 + ip) = h2(v0.x + v0.y, v1.x + v1.y); // ar+ai
    *reinterpret_cast<__half2*>(row + 1024 + ip) = h2(v0.z + v0.w, v1.z + v1.w); // aj+ak
    *reinterpret_cast<__half2*>(row + 2048 + ip) = h2(v0.y, v1.y);               // ai
    *reinterpret_cast<__half2*>(row + 3072 + ip) = h2(v0.w, v1.w);               // ak
    *reinterpret_cast<__half2*>(row + 4096 + ip) = h2(v0.x, v1.x);               // ar
    *reinterpret_cast<__half2*>(row + 5120 + ip) = h2(v0.z, v1.z);               // aj
}

// ---------------- Prep: B planes (signs folded) ----------------
__global__ void prep_b_kernel(const float4* __restrict__ w) {
    int t = blockIdx.x * blockDim.x + threadIdx.x;
    if (t >= NOUT * 512) return;
    int o  = t >> 9;
    int ip = (t & 511) << 1;
    const float4* wr = w + ((size_t)o * 1024 + ip);
    float4 v0 = wr[0], v1 = wr[1];
    __half* r0 = g_B0 + (size_t)o * KTOT;
    __half* r1 = g_B1 + (size_t)o * KTOT;
    // variant 0: [ br | -bj | -(br+bi) | bj-bk | bi-br | bj+bk ]
    *reinterpret_cast<__half2*>(r0 +    0 + ip) = h2( v0.x,           v1.x);
    *reinterpret_cast<__half2*>(r0 + 1024 + ip) = h2(-v0.z,          -v1.z);
    *reinterpret_cast<__half2*>(r0 + 2048 + ip) = h2(-(v0.x + v0.y), -(v1.x + v1.y));
    *reinterpret_cast<__half2*>(r0 + 3072 + ip) = h2( v0.z - v0.w,    v1.z - v1.w);
    *reinterpret_cast<__half2*>(r0 + 4096 + ip) = h2( v0.y - v0.x,    v1.y - v1.x);
    *reinterpret_cast<__half2*>(r0 + 5120 + ip) = h2( v0.z + v0.w,    v1.z + v1.w);
    // variant 1: [ bj | br | -(bj+bk) | bi-br | bk-bj | -(br+bi) ]
    *reinterpret_cast<__half2*>(r1 +    0 + ip) = h2( v0.z,           v1.z);
    *reinterpret_cast<__half2*>(r1 + 1024 + ip) = h2( v0.x,           v1.x);
    *reinterpret_cast<__half2*>(r1 + 2048 + ip) = h2(-(v0.z + v0.w), -(v1.z + v1.w));
    *reinterpret_cast<__half2*>(r1 + 3072 + ip) = h2( v0.y - v0.x,    v1.y - v1.x);
    *reinterpret_cast<__half2*>(r1 + 4096 + ip) = h2( v0.w - v0.z,    v1.w - v1.z);
    *reinterpret_cast<__half2*>(r1 + 5120 + ip) = h2(-(v0.x + v0.y), -(v1.x + v1.y));
}

// ---------------- GEMM ----------------
__device__ __forceinline__ void load_stage(uint32_t sbase, int slot, int kt,
                                           int m0, int n0o, int tid,
                                           const __half* __restrict__ Bmat) {
    uint32_t st = sbase + slot * STAGE_BYTES;
    int k0 = kt * BK;
    const __half* Ap = g_A  + (size_t)m0  * KTOT + k0;
    const __half* Bp = Bmat + (size_t)n0o * KTOT + k0;
#pragma unroll
    for (int c = 0; c < BM * 8; c += NTHREADS) {     // A: 1024 16B chunks
        int cc = c + tid;
        int row = cc >> 3, col = cc & 7;
        uint32_t sw = sw128((uint32_t)((row << 7) | (col << 4)));
        cp_async16(st + sw, Ap + (size_t)row * KTOT + (col << 3));
    }
#pragma unroll
    for (int c = 0; c < BN * 8; c += NTHREADS) {     // B: 2048 16B chunks
        int cc = c + tid;
        int row = cc >> 3, col = cc & 7;
        uint32_t sw = sw128((uint32_t)((row << 7) | (col << 4)));
        cp_async16(st + A_TILE_BYTES + sw, Bp + (size_t)row * KTOT + (col << 3));
    }
}

// One k-iteration: pipeline maintenance + 4 k-steps of mma into acc.
#define KITER(kvar)                                                               \
    do {                                                                          \
        CP_WAIT(STAGES - 2);                                                      \
        __syncthreads();                                                          \
        int kload = (kvar) + STAGES - 1;                                          \
        if (kload < NK) load_stage(sbase, kload % STAGES, kload, m0, n0o, tid, Bmat); \
        CP_COMMIT();                                                              \
        uint32_t a_base = sbase + ((kvar) % STAGES) * STAGE_BYTES;                \
        uint32_t b_base = a_base + A_TILE_BYTES;                                  \
        _Pragma("unroll")                                                         \
        for (int ks = 0; ks < BK / 16; ++ks) {                                    \
            int kb = ks * 32;                                                     \
            uint32_t af[4][4];                                                    \
            _Pragma("unroll")                                                     \
            for (int mt = 0; mt < 4; ++mt) {                                      \
                uint32_t off = (uint32_t)((a_row_base + mt * 16) << 7) + kb + a_kb_base; \
                ldm_x4(af[mt], a_base + sw128(off));                              \
            }                                                                     \
            uint32_t bf[4][4];                                                    \
            _Pragma("unroll")                                                     \
            for (int ntp = 0; ntp < 4; ++ntp) {                                   \
                uint32_t off = (uint32_t)((b_row_base + ntp * 16) << 7) + kb + b_kb_base; \
                ldm_x4(bf[ntp], b_base + sw128(off));                             \
            }                                                                     \
            _Pragma("unroll")                                                     \
            for (int mt = 0; mt < 4; ++mt)                                        \
                _Pragma("unroll")                                                 \
                for (int nt = 0; nt < 8; ++nt)                                    \
                    mma16816(acc[mt][nt], af[mt], &bf[nt >> 1][(nt & 1) * 2]);    \
        }                                                                         \
    } while (0)

__global__ void __launch_bounds__(NTHREADS, 1) qgemm_kernel(const float* __restrict__ bias,
                                                            float* __restrict__ out) {
    extern __shared__ char smem[];
    uint32_t sbase = smem_u32(smem);
    int tid = threadIdx.x;
    int wid = tid >> 5;
    int lid = tid & 31;
    int m0  = blockIdx.y * BM;         // batch rows
    int n0o = blockIdx.x * BN;         // o columns (0..1023 range, BN=256 span)
    const __half* Bmat = blockIdx.z ? g_B1 : g_B0;
    int zc = (int)blockIdx.z * 2;
    int cta_lin = ((int)blockIdx.z * 32 + (int)blockIdx.y) * 4 + (int)blockIdx.x;

    int warp_m = wid & 1;   // 2 warps along M (64 rows each)
    int warp_n = wid >> 1;  // 4 warps along N (64 cols each)

    float acc[4][8][4];
#pragma unroll
    for (int i = 0; i < 4; ++i)
#pragma unroll
        for (int j = 0; j < 8; ++j)
#pragma unroll
            for (int v = 0; v < 4; ++v) acc[i][j][v] = 0.f;

    // Prologue: stages 0 .. STAGES-2
#pragma unroll
    for (int s = 0; s < STAGES - 1; ++s) {
        load_stage(sbase, s, s, m0, n0o, tid, Bmat);
        CP_COMMIT();
    }

    // Per-lane ldmatrix address components (64x64 warp tile geometry)
    int a_mat = lid >> 3;            // 0..3
    int a_r   = lid & 7;
    int a_row_base = warp_m * 64 + (a_mat & 1) * 8 + a_r;   // + mt*16
    int a_kb_base  = (a_mat >> 1) * 16;
    int b_row_base = warp_n * 64 + (a_mat >> 1) * 8 + a_r;  // + ntp*16
    int b_kb_base  = (a_mat & 1) * 16;

    // Phase 1: K-blocks 0..1 (shared Gauss term)
    for (int k = 0; k < 32; ++k) KITER(k);

    // Snapshot acc -> g_S (coalesced: lanes write consecutive float4)
    {
        float* Sp = g_S + (size_t)cta_lin * (BM * BN) + tid * 4;
#pragma unroll
        for (int mt = 0; mt < 4; ++mt)
#pragma unroll
            for (int nt = 0; nt < 8; ++nt) {
                int j = mt * 8 + nt;
                float4 v = {acc[mt][nt][0], acc[mt][nt][1], acc[mt][nt][2], acc[mt][nt][3]};
                *reinterpret_cast<float4*>(Sp + (size_t)j * (NTHREADS * 4)) = v;
            }
    }

    // Phase 2: K-blocks 2..3 (completes comp zc: out_r / out_j)
    for (int k = 32; k < 64; ++k) KITER(k);

    // Epilogue A: write component zc
    int qrow = lid >> 2;        // 0..7
    int qcol = (lid & 3) * 2;   // 0,2,4,6
#pragma unroll
    for (int nt = 0; nt < 8; ++nt) {
        int o = n0o + warp_n * 64 + nt * 8 + qcol;   // o, o+1
        float b0 = __ldg(bias + o * 4 + zc);
        float b1 = __ldg(bias + (o + 1) * 4 + zc);
#pragma unroll
        for (int mt = 0; mt < 4; ++mt) {
            int gm = m0 + warp_m * 64 + mt * 16 + qrow;
            out[(size_t)gm * 4096 + o * 4 + zc]           = acc[mt][nt][0] + b0;
            out[(size_t)gm * 4096 + (o + 1) * 4 + zc]     = acc[mt][nt][1] + b1;
            out[(size_t)(gm + 8) * 4096 + o * 4 + zc]     = acc[mt][nt][2] + b0;
            out[(size_t)(gm + 8) * 4096 + (o + 1) * 4 + zc] = acc[mt][nt][3] + b1;
        }
    }

    // Reload snapshot: acc <- g_S
    {
        const float* Sp = g_S + (size_t)cta_lin * (BM * BN) + tid * 4;
#pragma unroll
        for (int mt = 0; mt < 4; ++mt)
#pragma unroll
            for (int nt = 0; nt < 8; ++nt) {
                int j = mt * 8 + nt;
                float4 v = *reinterpret_cast<const float4*>(Sp + (size_t)j * (NTHREADS * 4));
                acc[mt][nt][0] = v.x; acc[mt][nt][1] = v.y;
                acc[mt][nt][2] = v.z; acc[mt][nt][3] = v.w;
            }
    }

    // Phase 3: K-blocks 4..5 (completes comp zc+1: out_i / out_k)
    for (int k = 64; k < NK; ++k) KITER(k);

    // Epilogue B: write component zc+1
    int zc1 = zc + 1;
#pragma unroll
    for (int nt = 0; nt < 8; ++nt) {
        int o = n0o + warp_n * 64 + nt * 8 + qcol;
        float b0 = __ldg(bias + o * 4 + zc1);
        float b1 = __ldg(bias + (o + 1) * 4 + zc1);
#pragma unroll
        for (int mt = 0; mt < 4; ++mt) {
            int gm = m0 + warp_m * 64 + mt * 16 + qrow;
            out[(size_t)gm * 4096 + o * 4 + zc1]            = acc[mt][nt][0] + b0;
            out[(size_t)gm * 4096 + (o + 1) * 4 + zc1]      = acc[mt][nt][1] + b1;
            out[(size_t)(gm + 8) * 4096 + o * 4 + zc1]      = acc[mt][nt][2] + b0;
            out[(size_t)(gm + 8) * 4096 + (o + 1) * 4 + zc1] = acc[mt][nt][3] + b1;
        }
    }
}

// ---------------- launch ----------------
extern "C" void kernel_launch(void* const* d_in, const int* in_sizes, int n_in,
                              void* d_out, int out_size) {
    const float* x    = (const float*)d_in[0];
    const float* w    = (const float*)d_in[1];
    const float* bias = (const float*)d_in[2];
    float* out = (float*)d_out;

    prep_a_kernel<<<(BATCH * 512 + 255) / 256, 256>>>((const float4*)x);
    prep_b_kernel<<<(NOUT * 512 + 255) / 256, 256>>>((const float4*)w);

    cudaFuncSetAttribute(qgemm_kernel, cudaFuncAttributeMaxDynamicSharedMemorySize, SMEM_TOTAL);
    dim3 grid(NOUT / BN, BATCH / BM, 2);   // (4, 32, 2) = 256 CTAs
    qgemm_kernel<<<grid, NTHREADS, SMEM_TOTAL>>>(bias, out);
}

// round 12
// speedup vs baseline: 1.0951x; 1.0951x over previous
#include <cuda_runtime.h>
#include <cuda_fp16.h>
#include <cstdint>

// ============================================================
// QuaternionLinear via 12-mult Cayley-Dickson/Gauss decomposition.
// R11: 64x64 warp tiles (BN=256) with the shared-Gauss snapshot
// kept in SMEM as fp16 (swap trick), single coalesced float2
// epilogue writing both components. No global snapshot traffic.
//   variant0 (out_r,out_i): B0=[br|-bj|-(br+bi)|bj-bk|bi-br|bj+bk]
//   variant1 (out_j,out_k): B1=[bj|br|-(bj+bk)|bi-br|bk-bj|-(br+bi)]
//   A planes: q = [ar+ai, aj+ak, ai, ak, ar, aj]
// ============================================================

#define BATCH   4096
#define KTOT    6144
#define NOUT    1024

#define BM      128
#define BN      256
#define BK      64            // halves per K-tile (128B rows)
#define NK      (KTOT / BK)   // 96
#define STAGES  3
#define NTHREADS 256

#define A_TILE_BYTES (BM * 128)   // 16384
#define B_TILE_BYTES (BN * 128)   // 32768
#define STAGE_BYTES  (A_TILE_BYTES + B_TILE_BYTES)   // 49152
#define PIPE_BYTES   (STAGES * STAGE_BYTES)          // 147456
#define SNAP_OFF     PIPE_BYTES
#define SNAP_BYTES   (BM * BN * 2)                   // 65536 (fp16)
#define SMEM_TOTAL   (SNAP_OFF + SNAP_BYTES)         // 212992

// device-global scratch (allocation-free per harness rules)
__device__ __align__(128) __half g_A [(size_t)BATCH * KTOT];     // 50.3 MB
__device__ __align__(128) __half g_B0[(size_t)NOUT  * KTOT];     // 12.6 MB
__device__ __align__(128) __half g_B1[(size_t)NOUT  * KTOT];     // 12.6 MB

// ---------------- helpers ----------------
__device__ __forceinline__ uint32_t smem_u32(const void* p) {
    uint32_t a;
    asm("{ .reg .u64 t; cvta.to.shared.u64 t, %1; cvt.u32.u64 %0, t; }" : "=r"(a) : "l"(p));
    return a;
}
__device__ __forceinline__ void cp_async16(uint32_t dst, const void* src) {
    asm volatile("cp.async.cg.shared.global [%0], [%1], 16;\n" :: "r"(dst), "l"(src));
}
#define CP_COMMIT() asm volatile("cp.async.commit_group;\n" ::: "memory")
#define CP_WAIT(n)  asm volatile("cp.async.wait_group %0;\n" :: "n"(n) : "memory")

__device__ __forceinline__ void ldm_x4(uint32_t* r, uint32_t addr) {
    asm volatile("ldmatrix.sync.aligned.m8n8.x4.shared.b16 {%0,%1,%2,%3}, [%4];"
        : "=r"(r[0]), "=r"(r[1]), "=r"(r[2]), "=r"(r[3]) : "r"(addr));
}
__device__ __forceinline__ void mma16816(float* c, const uint32_t* a, const uint32_t* b) {
    asm volatile(
        "mma.sync.aligned.m16n8k16.row.col.f32.f16.f16.f32 "
        "{%0,%1,%2,%3}, {%4,%5,%6,%7}, {%8,%9}, {%0,%1,%2,%3};"
        : "+f"(c[0]), "+f"(c[1]), "+f"(c[2]), "+f"(c[3])
        : "r"(a[0]), "r"(a[1]), "r"(a[2]), "r"(a[3]), "r"(b[0]), "r"(b[1]));
}
__device__ __forceinline__ uint32_t sw128(uint32_t off) {
    return off ^ ((off >> 3) & 0x70);
}
__device__ __forceinline__ __half2 h2(float a, float b) { return __floats2half2_rn(a, b); }

// ---------------- Prep: A planes ----------------
__global__ void prep_a_kernel(const float4* __restrict__ x) {
    int t = blockIdx.x * blockDim.x + threadIdx.x;
    if (t >= BATCH * 512) return;
    int b  = t >> 9;
    int ip = (t & 511) << 1;
    const float4* xr = x + ((size_t)b * 1024 + ip);
    float4 v0 = xr[0], v1 = xr[1];
    __half* row = g_A + (size_t)b * KTOT;
    *reinterpret_cast<__half2*>(row +    0 + ip) = h2(v0.x + v0.y, v1.x + v1.y); // ar+ai
    *reinterpret_cast<__half2*>(row + 1024 + ip) = h2(v0.z + v0.w, v1.z + v1.w); // aj+ak
    *reinterpret_cast<__half2*>(row + 2048 + ip) = h2(v0.y, v1.y);               // ai
    *reinterpret_cast<__half2*>(row + 3072 + ip) = h2(v0.w, v1.w);               // ak
    *reinterpret_cast<__half2*>(row + 4096 + ip) = h2(v0.x, v1.x);               // ar
    *reinterpret_cast<__half2*>(row + 5120 + ip) = h2(v0.z, v1.z);               // aj
}

// ---------------- Prep: B planes (signs folded) ----------------
__global__ void prep_b_kernel(const float4* __restrict__ w) {
    int t = blockIdx.x * blockDim.x + threadIdx.x;
    if (t >= NOUT * 512) return;
    int o  = t >> 9;
    int ip = (t & 511) << 1;
    const float4* wr = w + ((size_t)o * 1024 + ip);
    float4 v0 = wr[0], v1 = wr[1];
    __half* r0 = g_B0 + (size_t)o * KTOT;
    __half* r1 = g_B1 + (size_t)o * KTOT;
    // variant 0: [ br | -bj | -(br+bi) | bj-bk | bi-br | bj+bk ]
    *reinterpret_cast<__half2*>(r0 +    0 + ip) = h2( v0.x,           v1.x);
    *reinterpret_cast<__half2*>(r0 + 1024 + ip) = h2(-v0.z,          -v1.z);
    *reinterpret_cast<__half2*>(r0 + 2048 + ip) = h2(-(v0.x + v0.y), -(v1.x + v1.y));
    *reinterpret_cast<__half2*>(r0 + 3072 + ip) = h2( v0.z - v0.w,    v1.z - v1.w);
    *reinterpret_cast<__half2*>(r0 + 4096 + ip) = h2( v0.y - v0.x,    v1.y - v1.x);
    *reinterpret_cast<__half2*>(r0 + 5120 + ip) = h2( v0.z + v0.w,    v1.z + v1.w);
    // variant 1: [ bj | br | -(bj+bk) | bi-br | bk-bj | -(br+bi) ]
    *reinterpret_cast<__half2*>(r1 +    0 + ip) = h2( v0.z,           v1.z);
    *reinterpret_cast<__half2*>(r1 + 1024 + ip) = h2( v0.x,           v1.x);
    *reinterpret_cast<__half2*>(r1 + 2048 + ip) = h2(-(v0.z + v0.w), -(v1.z + v1.w));
    *reinterpret_cast<__half2*>(r1 + 3072 + ip) = h2( v0.y - v0.x,    v1.y - v1.x);
    *reinterpret_cast<__half2*>(r1 + 4096 + ip) = h2( v0.w - v0.z,    v1.w - v1.z);
    *reinterpret_cast<__half2*>(r1 + 5120 + ip) = h2(-(v0.x + v0.y), -(v1.x + v1.y));
}

// ---------------- GEMM ----------------
__device__ __forceinline__ void load_stage(uint32_t sbase, int slot, int kt,
                                           int m0, int n0o, int tid,
                                           const __half* __restrict__ Bmat) {
    uint32_t st = sbase + slot * STAGE_BYTES;
    int k0 = kt * BK;
    const __half* Ap = g_A  + (size_t)m0  * KTOT + k0;
    const __half* Bp = Bmat + (size_t)n0o * KTOT + k0;
#pragma unroll
    for (int c = 0; c < BM * 8; c += NTHREADS) {     // A: 1024 16B chunks
        int cc = c + tid;
        int row = cc >> 3, col = cc & 7;
        uint32_t sw = sw128((uint32_t)((row << 7) | (col << 4)));
        cp_async16(st + sw, Ap + (size_t)row * KTOT + (col << 3));
    }
#pragma unroll
    for (int c = 0; c < BN * 8; c += NTHREADS) {     // B: 2048 16B chunks
        int cc = c + tid;
        int row = cc >> 3, col = cc & 7;
        uint32_t sw = sw128((uint32_t)((row << 7) | (col << 4)));
        cp_async16(st + A_TILE_BYTES + sw, Bp + (size_t)row * KTOT + (col << 3));
    }
}

// One k-iteration: pipeline maintenance + 4 k-steps of mma into acc.
#define KITER(kvar)                                                               \
    do {                                                                          \
        CP_WAIT(STAGES - 2);                                                      \
        __syncthreads();                                                          \
        int kload = (kvar) + STAGES - 1;                                          \
        if (kload < NK) load_stage(sbase, kload % STAGES, kload, m0, n0o, tid, Bmat); \
        CP_COMMIT();                                                              \
        uint32_t a_base = sbase + ((kvar) % STAGES) * STAGE_BYTES;                \
        uint32_t b_base = a_base + A_TILE_BYTES;                                  \
        _Pragma("unroll")                                                         \
        for (int ks = 0; ks < BK / 16; ++ks) {                                    \
            int kb = ks * 32;                                                     \
            uint32_t af[4][4];                                                    \
            _Pragma("unroll")                                                     \
            for (int mt = 0; mt < 4; ++mt) {                                      \
                uint32_t off = (uint32_t)((a_row_base + mt * 16) << 7) + kb + a_kb_base; \
                ldm_x4(af[mt], a_base + sw128(off));                              \
            }                                                                     \
            uint32_t bf[4][4];                                                    \
            _Pragma("unroll")                                                     \
            for (int ntp = 0; ntp < 4; ++ntp) {                                   \
                uint32_t off = (uint32_t)((b_row_base + ntp * 16) << 7) + kb + b_kb_base; \
                ldm_x4(bf[ntp], b_base + sw128(off));                             \
            }                                                                     \
            _Pragma("unroll")                                                     \
            for (int mt = 0; mt < 4; ++mt)                                        \
                _Pragma("unroll")                                                 \
                for (int nt = 0; nt < 8; ++nt)                                    \
                    mma16816(acc[mt][nt], af[mt], &bf[nt >> 1][(nt & 1) * 2]);    \
        }                                                                         \
    } while (0)

__global__ void __launch_bounds__(NTHREADS, 1) qgemm_kernel(const float* __restrict__ bias,
                                                            float* __restrict__ out) {
    extern __shared__ char smem[];
    uint32_t sbase = smem_u32(smem);
    int tid = threadIdx.x;
    int wid = tid >> 5;
    int lid = tid & 31;
    int m0  = blockIdx.y * BM;         // batch rows
    int n0o = blockIdx.x * BN;         // o columns
    const __half* Bmat = blockIdx.z ? g_B1 : g_B0;
    int zc = (int)blockIdx.z * 2;

    __half2* S = reinterpret_cast<__half2*>(smem + SNAP_OFF);  // per-thread slots

    int warp_m = wid & 1;   // 2 warps along M (64 rows each)
    int warp_n = wid >> 1;  // 4 warps along N (64 cols each)

    float acc[4][8][4];
#pragma unroll
    for (int i = 0; i < 4; ++i)
#pragma unroll
        for (int j = 0; j < 8; ++j)
#pragma unroll
            for (int v = 0; v < 4; ++v) acc[i][j][v] = 0.f;

    // Prologue: stages 0 .. STAGES-2
#pragma unroll
    for (int s = 0; s < STAGES - 1; ++s) {
        load_stage(sbase, s, s, m0, n0o, tid, Bmat);
        CP_COMMIT();
    }

    // Per-lane ldmatrix address components (64x64 warp tile geometry)
    int a_mat = lid >> 3;            // 0..3
    int a_r   = lid & 7;
    int a_row_base = warp_m * 64 + (a_mat & 1) * 8 + a_r;   // + mt*16
    int a_kb_base  = (a_mat >> 1) * 16;
    int b_row_base = warp_n * 64 + (a_mat >> 1) * 8 + a_r;  // + ntp*16
    int b_kb_base  = (a_mat & 1) * 16;

    // Phase 1: K-blocks 0..1 (shared Gauss term)
    for (int k = 0; k < 32; ++k) KITER(k);

    // Snapshot acc -> smem fp16 (per-thread private slots, conflict-free)
#pragma unroll
    for (int mt = 0; mt < 4; ++mt)
#pragma unroll
        for (int nt = 0; nt < 8; ++nt) {
            int jb = (mt * 8 + nt) * 2;
            S[(jb + 0) * NTHREADS + tid] = h2(acc[mt][nt][0], acc[mt][nt][1]);
            S[(jb + 1) * NTHREADS + tid] = h2(acc[mt][nt][2], acc[mt][nt][3]);
        }

    // Phase 2: K-blocks 2..3 (acc completes comp zc)
    for (int k = 32; k < 64; ++k) KITER(k);

    // Swap: snap <- comp-zc result; acc <- shared Gauss term
#pragma unroll
    for (int mt = 0; mt < 4; ++mt)
#pragma unroll
        for (int nt = 0; nt < 8; ++nt) {
            int jb = (mt * 8 + nt) * 2;
            __half2 o0 = S[(jb + 0) * NTHREADS + tid];
            __half2 o1 = S[(jb + 1) * NTHREADS + tid];
            S[(jb + 0) * NTHREADS + tid] = h2(acc[mt][nt][0], acc[mt][nt][1]);
            S[(jb + 1) * NTHREADS + tid] = h2(acc[mt][nt][2], acc[mt][nt][3]);
            float2 f0 = __half22float2(o0);
            float2 f1 = __half22float2(o1);
            acc[mt][nt][0] = f0.x; acc[mt][nt][1] = f0.y;
            acc[mt][nt][2] = f1.x; acc[mt][nt][3] = f1.y;
        }

    // Phase 3: K-blocks 4..5 (acc completes comp zc+1)
    for (int k = 64; k < NK; ++k) KITER(k);

    // Combined epilogue: comp zc from smem, comp zc+1 from acc -> float2 stores
    int qrow = lid >> 2;        // 0..7
    int qcol = (lid & 3) * 2;   // 0,2,4,6
#pragma unroll
    for (int nt = 0; nt < 8; ++nt) {
        int o = n0o + warp_n * 64 + nt * 8 + qcol;   // o, o+1
        float2 bo  = *reinterpret_cast<const float2*>(bias + o * 4 + zc);
        float2 bo1 = *reinterpret_cast<const float2*>(bias + (o + 1) * 4 + zc);
#pragma unroll
        for (int mt = 0; mt < 4; ++mt) {
            int gm = m0 + warp_m * 64 + mt * 16 + qrow;
            int jb = (mt * 8 + nt) * 2;
            float2 s0 = __half22float2(S[(jb + 0) * NTHREADS + tid]);  // zc: (qrow,o),(qrow,o+1)
            float2 s1 = __half22float2(S[(jb + 1) * NTHREADS + tid]);  // zc: (qrow+8,o),(qrow+8,o+1)
            float2 v;
            v.x = s0.x + bo.x;  v.y = acc[mt][nt][0] + bo.y;
            *reinterpret_cast<float2*>(out + (size_t)gm * 4096 + o * 4 + zc) = v;
            v.x = s0.y + bo1.x; v.y = acc[mt][nt][1] + bo1.y;
            *reinterpret_cast<float2*>(out + (size_t)gm * 4096 + (o + 1) * 4 + zc) = v;
            v.x = s1.x + bo.x;  v.y = acc[mt][nt][2] + bo.y;
            *reinterpret_cast<float2*>(out + (size_t)(gm + 8) * 4096 + o * 4 + zc) = v;
            v.x = s1.y + bo1.x; v.y = acc[mt][nt][3] + bo1.y;
            *reinterpret_cast<float2*>(out + (size_t)(gm + 8) * 4096 + (o + 1) * 4 + zc) = v;
        }
    }
}

// ---------------- launch ----------------
extern "C" void kernel_launch(void* const* d_in, const int* in_sizes, int n_in,
                              void* d_out, int out_size) {
    const float* x    = (const float*)d_in[0];
    const float* w    = (const float*)d_in[1];
    const float* bias = (const float*)d_in[2];
    float* out = (float*)d_out;

    prep_a_kernel<<<(BATCH * 512 + 255) / 256, 256>>>((const float4*)x);
    prep_b_kernel<<<(NOUT * 512 + 255) / 256, 256>>>((const float4*)w);

    cudaFuncSetAttribute(qgemm_kernel, cudaFuncAttributeMaxDynamicSharedMemorySize, SMEM_TOTAL);
    dim3 grid(NOUT / BN, BATCH / BM, 2);   // (4, 32, 2) = 256 CTAs
    qgemm_kernel<<<grid, NTHREADS, SMEM_TOTAL>>>(bias, out);
}